// round 4
// baseline (speedup 1.0000x reference)
#include <cuda_runtime.h>
#include <cuda_bf16.h>

// Problem constants (fixed by the reference)
#define NN 50000
#define EE 800000
#define HH 128

// Scratch (no cudaMalloc allowed)
__device__ int   g_deg[NN];
__device__ float g_dinv[NN];
__device__ float g_xw[NN * HH];   // x @ W (layer input transformed)
__device__ float g_h[NN * HH];    // layer-1 accumulator / hidden activations

// ---------------------------------------------------------------------------
// deg[i] = 1 (self loop)
__global__ void k_init_deg(int n) {
    int i = blockIdx.x * blockDim.x + threadIdx.x;
    if (i < n) g_deg[i] = 1;
}

// deg[row[e]] += 1
__global__ void k_count_deg(const int* __restrict__ rows, int e) {
    int i = blockIdx.x * blockDim.x + threadIdx.x;
    if (i < e) atomicAdd(&g_deg[rows[i]], 1);
}

// dinv[i] = rsqrt(deg[i])   (deg >= 1 always due to self loop)
__global__ void k_dinv(int n) {
    int i = blockIdx.x * blockDim.x + threadIdx.x;
    if (i < n) g_dinv[i] = rsqrtf((float)g_deg[i]);
}

// ---------------------------------------------------------------------------
// Y[n,128] = X[n,128] @ W[128,128]
// 128 threads/block, 4 nodes per block iteration. W column t cached in L1;
// each W element reused across 4 node accumulators.
__global__ void k_gemm128(const float* __restrict__ X, const float* __restrict__ W,
                          float* __restrict__ Y, int n) {
    __shared__ float xs[4][HH];
    const int t = threadIdx.x;
    for (int base = blockIdx.x * 4; base < n; base += gridDim.x * 4) {
        #pragma unroll
        for (int i = 0; i < 4; i++) {
            int node = base + i;
            xs[i][t] = (node < n) ? X[node * HH + t] : 0.0f;
        }
        __syncthreads();
        float a0 = 0.f, a1 = 0.f, a2 = 0.f, a3 = 0.f;
        #pragma unroll
        for (int k = 0; k < HH; k++) {
            float w = __ldg(&W[k * HH + t]);
            a0 = fmaf(xs[0][k], w, a0);
            a1 = fmaf(xs[1][k], w, a1);
            a2 = fmaf(xs[2][k], w, a2);
            a3 = fmaf(xs[3][k], w, a3);
        }
        if (base + 0 < n) Y[(base + 0) * HH + t] = a0;
        if (base + 1 < n) Y[(base + 1) * HH + t] = a1;
        if (base + 2 < n) Y[(base + 2) * HH + t] = a2;
        if (base + 3 < n) Y[(base + 3) * HH + t] = a3;
        __syncthreads();
    }
}

// ---------------------------------------------------------------------------
// OUT[i] = b + dinv[i]^2 * XW[i]    (self-loop message + bias, init accumulator)
__global__ void k_init_out(const float* __restrict__ XW, const float* __restrict__ b,
                           float* __restrict__ OUT, int n) {
    int i = blockIdx.x * blockDim.x + threadIdx.x;  // over n*128
    if (i < n * HH) {
        int node = i >> 7;
        int c = i & 127;
        float d = g_dinv[node];
        OUT[i] = b[c] + d * d * XW[i];
    }
}

// ---------------------------------------------------------------------------
// One warp per edge: OUT[row] += dinv[row]*dinv[col] * XW[col]
// float4 atomics (sm_90+) -> 32 vector REDs per edge instead of 128 scalar.
__global__ void k_scatter(const float4* __restrict__ XW,
                          const int* __restrict__ rows, const int* __restrict__ cols,
                          float4* __restrict__ OUT, int e) {
    int warp = blockIdx.x * (blockDim.x >> 5) + (threadIdx.x >> 5);
    if (warp >= e) return;
    int lane = threadIdx.x & 31;
    int r = __ldg(&rows[warp]);
    int c = __ldg(&cols[warp]);
    float nrm = g_dinv[r] * g_dinv[c];
    float4 v = XW[c * 32 + lane];
    v.x *= nrm; v.y *= nrm; v.z *= nrm; v.w *= nrm;
    atomicAdd(&OUT[r * 32 + lane], v);
}

// ---------------------------------------------------------------------------
__global__ void k_relu(float* __restrict__ A, int total) {
    int i = blockIdx.x * blockDim.x + threadIdx.x;
    if (i < total) A[i] = fmaxf(A[i], 0.0f);
}

// ---------------------------------------------------------------------------
extern "C" void kernel_launch(void* const* d_in, const int* in_sizes, int n_in,
                              void* d_out, int out_size) {
    const float* x    = (const float*)d_in[0];
    const int*   ei   = (const int*)d_in[1];     // [2, E] row-major
    const float* W1   = (const float*)d_in[2];
    const float* b1   = (const float*)d_in[3];
    const float* W2   = (const float*)d_in[4];
    const float* b2   = (const float*)d_in[5];
    float*       out  = (float*)d_out;

    const int n = NN;
    const int e = EE;
    const int* rows = ei;        // edge_index[0]
    const int* cols = ei + e;    // edge_index[1]

    float* xw; cudaGetSymbolAddress((void**)&xw, g_xw);
    float* h;  cudaGetSymbolAddress((void**)&h,  g_h);

    // --- normalization ---
    k_init_deg<<<(n + 255) / 256, 256>>>(n);
    k_count_deg<<<(e + 255) / 256, 256>>>(rows, e);
    k_dinv<<<(n + 255) / 256, 256>>>(n);

    const int total = n * HH;
    const int gemm_blocks = (n + 3) / 4;
    const int scat_blocks = (e + 7) / 8;   // 8 warps per 256-thread block

    // --- layer 1 ---
    k_gemm128<<<gemm_blocks, 128>>>(x, W1, xw, n);
    k_init_out<<<(total + 255) / 256, 256>>>(xw, b1, h, n);
    k_scatter<<<scat_blocks, 256>>>((const float4*)xw, rows, cols, (float4*)h, e);
    k_relu<<<(total + 255) / 256, 256>>>(h, total);

    // --- layer 2 ---
    k_gemm128<<<gemm_blocks, 128>>>(h, W2, xw, n);
    k_init_out<<<(total + 255) / 256, 256>>>(xw, b2, out, n);
    k_scatter<<<scat_blocks, 256>>>((const float4*)xw, rows, cols, (float4*)out, e);
}

// round 5
// speedup vs baseline: 1.4294x; 1.4294x over previous
#include <cuda_runtime.h>
#include <cuda_bf16.h>

// Problem constants (fixed by the reference)
#define NN 50000
#define EE 800000
#define HH 128

// Scratch (no cudaMalloc allowed)
__device__ int   g_deg[NN];
__device__ float g_dinv[NN];
__device__ int   g_rowptr[NN + 1];
__device__ int   g_fill[NN];
__device__ int2  g_edges[EE];          // {col, __float_as_int(norm)} grouped by row
__device__ float g_xw[NN * HH];        // X @ W
__device__ float g_h[NN * HH];         // hidden activations

// ---------------------------------------------------------------------------
// packed fp32 helpers (Blackwell f32x2 pipe — 2 fp32 FMA per issue)
__device__ __forceinline__ unsigned long long ffma2(unsigned long long a,
                                                    unsigned long long b,
                                                    unsigned long long c) {
    unsigned long long d;
    asm("fma.rn.f32x2 %0, %1, %2, %3;" : "=l"(d) : "l"(a), "l"(b), "l"(c));
    return d;
}
__device__ __forceinline__ unsigned long long pack2(float lo, float hi) {
    unsigned long long d;
    asm("mov.b64 %0, {%1, %2};" : "=l"(d) : "f"(lo), "f"(hi));
    return d;
}
__device__ __forceinline__ void unpack2(unsigned long long p, float& lo, float& hi) {
    asm("mov.b64 {%0, %1}, %2;" : "=f"(lo), "=f"(hi) : "l"(p));
}

// ---------------------------------------------------------------------------
// deg[i]=1 (self loop), fill[i]=0
__global__ void k_init(int n) {
    int i = blockIdx.x * blockDim.x + threadIdx.x;
    if (i < n) { g_deg[i] = 1; g_fill[i] = 0; }
}

__global__ void k_count_deg(const int* __restrict__ rows, int e) {
    int i = blockIdx.x * blockDim.x + threadIdx.x;
    if (i < e) atomicAdd(&g_deg[rows[i]], 1);
}

__global__ void k_dinv(int n) {
    int i = blockIdx.x * blockDim.x + threadIdx.x;
    if (i < n) g_dinv[i] = rsqrtf((float)g_deg[i]);
}

// Single-block exclusive scan of (deg[i]-1) -> rowptr
__global__ void k_scan() {
    __shared__ int s[1024];
    const int tid = threadIdx.x;
    const int CH = (NN + 1023) / 1024;   // 49
    const int start = tid * CH;
    int sum = 0;
    for (int i = 0; i < CH; i++) {
        int idx = start + i;
        if (idx < NN) sum += g_deg[idx] - 1;
    }
    s[tid] = sum;
    __syncthreads();
    for (int off = 1; off < 1024; off <<= 1) {
        int v = (tid >= off) ? s[tid - off] : 0;
        __syncthreads();
        s[tid] += v;
        __syncthreads();
    }
    int run = (tid == 0) ? 0 : s[tid - 1];
    for (int i = 0; i < CH; i++) {
        int idx = start + i;
        if (idx < NN) { g_rowptr[idx] = run; run += g_deg[idx] - 1; }
    }
    if (tid == 1023) g_rowptr[NN] = s[1023];
}

// Bucket edges by destination row; store {col, norm} per slot.
__global__ void k_fill(const int* __restrict__ rows, const int* __restrict__ cols, int e) {
    int i = blockIdx.x * blockDim.x + threadIdx.x;
    if (i < e) {
        int r = rows[i];
        int c = cols[i];
        int pos = g_rowptr[r] + atomicAdd(&g_fill[r], 1);
        float nrm = g_dinv[r] * g_dinv[c];
        g_edges[pos] = make_int2(c, __float_as_int(nrm));
    }
}

// ---------------------------------------------------------------------------
// Y[n,128] = X[n,128] @ W[128,128], packed-f32x2 inner loop.
// 128 threads (t = output column), 16 nodes per tile, persistent blocks.
__global__ void __launch_bounds__(128) k_gemm128(const float* __restrict__ X,
                                                 const float* __restrict__ W,
                                                 float* __restrict__ Y) {
    __shared__ float xsT[HH * 20];   // [k][node], row stride 20 (16B-aligned rows)
    const int t = threadIdx.x;
    const int NTILES = NN / 16;      // 3125

    for (int tile = blockIdx.x; tile < NTILES; tile += gridDim.x) {
        const int base = tile * 16;
        // load + transpose: thread t owns k=t, loads 16 node values (coalesced)
        {
            float v[16];
            #pragma unroll
            for (int n = 0; n < 16; n++) v[n] = X[(base + n) * HH + t];
            float* row = &xsT[t * 20];
            *(float4*)(row + 0)  = make_float4(v[0],  v[1],  v[2],  v[3]);
            *(float4*)(row + 4)  = make_float4(v[4],  v[5],  v[6],  v[7]);
            *(float4*)(row + 8)  = make_float4(v[8],  v[9],  v[10], v[11]);
            *(float4*)(row + 12) = make_float4(v[12], v[13], v[14], v[15]);
        }
        __syncthreads();

        unsigned long long acc[8];
        #pragma unroll
        for (int p = 0; p < 8; p++) acc[p] = 0ull;

        #pragma unroll 16
        for (int k = 0; k < HH; k++) {
            float w = __ldg(&W[k * HH + t]);
            unsigned long long w2 = pack2(w, w);
            const ulonglong2* xr = (const ulonglong2*)&xsT[k * 20];
            ulonglong2 p0 = xr[0];   // nodes 0-3
            ulonglong2 p1 = xr[1];   // nodes 4-7
            ulonglong2 p2 = xr[2];   // nodes 8-11
            ulonglong2 p3 = xr[3];   // nodes 12-15
            acc[0] = ffma2(p0.x, w2, acc[0]);
            acc[1] = ffma2(p0.y, w2, acc[1]);
            acc[2] = ffma2(p1.x, w2, acc[2]);
            acc[3] = ffma2(p1.y, w2, acc[3]);
            acc[4] = ffma2(p2.x, w2, acc[4]);
            acc[5] = ffma2(p2.y, w2, acc[5]);
            acc[6] = ffma2(p3.x, w2, acc[6]);
            acc[7] = ffma2(p3.y, w2, acc[7]);
        }

        #pragma unroll
        for (int p = 0; p < 8; p++) {
            float lo, hi;
            unpack2(acc[p], lo, hi);
            Y[(base + 2 * p + 0) * HH + t] = lo;
            Y[(base + 2 * p + 1) * HH + t] = hi;
        }
        __syncthreads();
    }
}

// ---------------------------------------------------------------------------
// One warp per destination row: OUT[r] = [relu]( b + dinv[r]^2*XW[r] + sum norm*XW[col] )
__global__ void __launch_bounds__(256) k_aggregate(const float4* __restrict__ XW,
                                                   const float4* __restrict__ b4,
                                                   float4* __restrict__ OUT,
                                                   int relu) {
    int r = blockIdx.x * (blockDim.x >> 5) + (threadIdx.x >> 5);
    if (r >= NN) return;
    int lane = threadIdx.x & 31;

    float dr = g_dinv[r];
    float s = dr * dr;
    float4 xv = XW[r * 32 + lane];
    float4 bb = b4[lane];
    float4 acc = make_float4(fmaf(s, xv.x, bb.x), fmaf(s, xv.y, bb.y),
                             fmaf(s, xv.z, bb.z), fmaf(s, xv.w, bb.w));

    int j = g_rowptr[r];
    const int end = g_rowptr[r + 1];
    if (j < end) {
        int2 e0 = g_edges[j];
        for (++j; j <= end; ++j) {
            int2 en;
            if (j < end) en = g_edges[j];       // prefetch next edge record
            float4 v = XW[e0.x * 32 + lane];
            float nrm = __int_as_float(e0.y);
            acc.x = fmaf(nrm, v.x, acc.x);
            acc.y = fmaf(nrm, v.y, acc.y);
            acc.z = fmaf(nrm, v.z, acc.z);
            acc.w = fmaf(nrm, v.w, acc.w);
            e0 = en;
        }
    }
    if (relu) {
        acc.x = fmaxf(acc.x, 0.f); acc.y = fmaxf(acc.y, 0.f);
        acc.z = fmaxf(acc.z, 0.f); acc.w = fmaxf(acc.w, 0.f);
    }
    OUT[r * 32 + lane] = acc;
}

// ---------------------------------------------------------------------------
extern "C" void kernel_launch(void* const* d_in, const int* in_sizes, int n_in,
                              void* d_out, int out_size) {
    const float* x   = (const float*)d_in[0];
    const int*   ei  = (const int*)d_in[1];     // [2, E] row-major
    const float* W1  = (const float*)d_in[2];
    const float* b1  = (const float*)d_in[3];
    const float* W2  = (const float*)d_in[4];
    const float* b2  = (const float*)d_in[5];
    float*       out = (float*)d_out;

    const int n = NN, e = EE;
    const int* rows = ei;
    const int* cols = ei + e;

    float* xw; cudaGetSymbolAddress((void**)&xw, g_xw);
    float* h;  cudaGetSymbolAddress((void**)&h,  g_h);

    // --- normalization + CSR build (graph shared by both layers) ---
    k_init<<<(n + 255) / 256, 256>>>(n);
    k_count_deg<<<(e + 255) / 256, 256>>>(rows, e);
    k_dinv<<<(n + 255) / 256, 256>>>(n);
    k_scan<<<1, 1024>>>();
    k_fill<<<(e + 255) / 256, 256>>>(rows, cols, e);

    const int gemm_blocks = 148 * 4;
    const int agg_blocks  = (n + 7) / 8;   // 8 warps (rows) per 256-thread block

    // --- layer 1 ---
    k_gemm128<<<gemm_blocks, 128>>>(x, W1, xw);
    k_aggregate<<<agg_blocks, 256>>>((const float4*)xw, (const float4*)b1, (float4*)h, 1);

    // --- layer 2 ---
    k_gemm128<<<gemm_blocks, 128>>>(h, W2, xw);
    k_aggregate<<<agg_blocks, 256>>>((const float4*)xw, (const float4*)b2, (float4*)out, 0);
}

// round 7
// speedup vs baseline: 1.7086x; 1.1954x over previous
#include <cuda_runtime.h>
#include <cuda_bf16.h>

// Problem constants (fixed by the reference)
#define NN 50000
#define EE 800000
#define HH 128
#define SCAN_NB 196   // ceil(NN/256)

// Scratch (no cudaMalloc allowed)
__device__ int   g_deg[NN];
__device__ float g_dinv[NN];
__device__ int   g_rowptr[NN + 1];
__device__ int   g_fill[NN];
__device__ int   g_bsum[256];          // per-block sums (padded)
__device__ int   g_boff[256];          // exclusive offsets of block sums
__device__ int2  g_edges[EE];          // {col, __float_as_int(norm)} grouped by row
__device__ float g_xw[NN * HH];        // X @ W
__device__ float g_h[NN * HH];         // hidden activations

// ---------------------------------------------------------------------------
// packed fp32 helpers (Blackwell f32x2 pipe — 2 fp32 FMA per issue)
__device__ __forceinline__ unsigned long long ffma2(unsigned long long a,
                                                    unsigned long long b,
                                                    unsigned long long c) {
    unsigned long long d;
    asm("fma.rn.f32x2 %0, %1, %2, %3;" : "=l"(d) : "l"(a), "l"(b), "l"(c));
    return d;
}
__device__ __forceinline__ unsigned long long pack2(float lo, float hi) {
    unsigned long long d;
    asm("mov.b64 %0, {%1, %2};" : "=l"(d) : "f"(lo), "f"(hi));
    return d;
}
__device__ __forceinline__ void unpack2(unsigned long long p, float& lo, float& hi) {
    asm("mov.b64 {%0, %1}, %2;" : "=f"(lo), "=f"(hi) : "l"(p));
}

// ---------------------------------------------------------------------------
__global__ void k_init(int n) {
    int i = blockIdx.x * blockDim.x + threadIdx.x;
    if (i < n) { g_deg[i] = 1; g_fill[i] = 0; }
}

__global__ void k_count_deg(const int* __restrict__ rows, int e) {
    int i = blockIdx.x * blockDim.x + threadIdx.x;
    if (i < e) atomicAdd(&g_deg[rows[i]], 1);
}

// ---------------------------------------------------------------------------
// Scan phase 1: per-block sum of (deg-1); also computes dinv (fused).
__global__ void __launch_bounds__(256) k_scan_blocks() {
    __shared__ int ws[8];
    int i = blockIdx.x * 256 + threadIdx.x;
    int v = 0;
    if (i < NN) {
        int d = g_deg[i];
        g_dinv[i] = rsqrtf((float)d);
        v = d - 1;
    }
    int s = v;
    #pragma unroll
    for (int o = 1; o < 32; o <<= 1) {
        int t = __shfl_up_sync(0xffffffffu, s, o);
        if ((threadIdx.x & 31) >= o) s += t;
    }
    if ((threadIdx.x & 31) == 31) ws[threadIdx.x >> 5] = s;
    __syncthreads();
    if (threadIdx.x == 0) {
        int tot = 0;
        #pragma unroll
        for (int w = 0; w < 8; w++) tot += ws[w];
        g_bsum[blockIdx.x] = tot;
    }
}

// Scan phase 2: exclusive scan of 196 block sums (1 block, 256 threads).
__global__ void __launch_bounds__(256) k_scan_tops() {
    __shared__ int ws[8];
    int t = threadIdx.x;
    int v = (t < SCAN_NB) ? g_bsum[t] : 0;
    int s = v;
    #pragma unroll
    for (int o = 1; o < 32; o <<= 1) {
        int u = __shfl_up_sync(0xffffffffu, s, o);
        if ((t & 31) >= o) s += u;
    }
    if ((t & 31) == 31) ws[t >> 5] = s;
    __syncthreads();
    int woff = 0;
    #pragma unroll
    for (int w = 0; w < 8; w++) {
        if (w < (t >> 5)) woff += ws[w];
    }
    if (t < SCAN_NB) g_boff[t] = woff + s - v;   // exclusive
    if (t == 0) g_rowptr[NN] = EE;               // sum(deg-1) == E by construction
}

// Scan phase 3: full exclusive scan -> rowptr.
__global__ void __launch_bounds__(256) k_scan_write() {
    __shared__ int ws[8];
    int i = blockIdx.x * 256 + threadIdx.x;
    int v = (i < NN) ? (g_deg[i] - 1) : 0;
    int s = v;
    #pragma unroll
    for (int o = 1; o < 32; o <<= 1) {
        int t = __shfl_up_sync(0xffffffffu, s, o);
        if ((threadIdx.x & 31) >= o) s += t;
    }
    if ((threadIdx.x & 31) == 31) ws[threadIdx.x >> 5] = s;
    __syncthreads();
    int woff = 0;
    #pragma unroll
    for (int w = 0; w < 8; w++) {
        if (w < (int)(threadIdx.x >> 5)) woff += ws[w];
    }
    if (i < NN) g_rowptr[i] = g_boff[blockIdx.x] + woff + s - v;
}

// ---------------------------------------------------------------------------
// Bucket edges by destination row; store {col, norm} per slot.
__global__ void k_fill(const int* __restrict__ rows, const int* __restrict__ cols, int e) {
    int i = blockIdx.x * blockDim.x + threadIdx.x;
    if (i < e) {
        int r = rows[i];
        int c = cols[i];
        int pos = g_rowptr[r] + atomicAdd(&g_fill[r], 1);
        float nrm = g_dinv[r] * g_dinv[c];
        g_edges[pos] = make_int2(c, __float_as_int(nrm));
    }
}

// ---------------------------------------------------------------------------
// Y[n,128] = X[n,128] @ W[128,128], packed-f32x2 inner loop.
__global__ void __launch_bounds__(128) k_gemm128(const float* __restrict__ X,
                                                 const float* __restrict__ W,
                                                 float* __restrict__ Y) {
    __shared__ float xsT[HH * 20];   // [k][node], row stride 20 (16B-aligned rows)
    const int t = threadIdx.x;
    const int NTILES = NN / 16;      // 3125

    for (int tile = blockIdx.x; tile < NTILES; tile += gridDim.x) {
        const int base = tile * 16;
        {
            float v[16];
            #pragma unroll
            for (int n = 0; n < 16; n++) v[n] = X[(base + n) * HH + t];
            float* row = &xsT[t * 20];
            *(float4*)(row + 0)  = make_float4(v[0],  v[1],  v[2],  v[3]);
            *(float4*)(row + 4)  = make_float4(v[4],  v[5],  v[6],  v[7]);
            *(float4*)(row + 8)  = make_float4(v[8],  v[9],  v[10], v[11]);
            *(float4*)(row + 12) = make_float4(v[12], v[13], v[14], v[15]);
        }
        __syncthreads();

        unsigned long long acc[8];
        #pragma unroll
        for (int p = 0; p < 8; p++) acc[p] = 0ull;

        #pragma unroll 16
        for (int k = 0; k < HH; k++) {
            float w = __ldg(&W[k * HH + t]);
            unsigned long long w2 = pack2(w, w);
            const ulonglong2* xr = (const ulonglong2*)&xsT[k * 20];
            ulonglong2 p0 = xr[0];
            ulonglong2 p1 = xr[1];
            ulonglong2 p2 = xr[2];
            ulonglong2 p3 = xr[3];
            acc[0] = ffma2(p0.x, w2, acc[0]);
            acc[1] = ffma2(p0.y, w2, acc[1]);
            acc[2] = ffma2(p1.x, w2, acc[2]);
            acc[3] = ffma2(p1.y, w2, acc[3]);
            acc[4] = ffma2(p2.x, w2, acc[4]);
            acc[5] = ffma2(p2.y, w2, acc[5]);
            acc[6] = ffma2(p3.x, w2, acc[6]);
            acc[7] = ffma2(p3.y, w2, acc[7]);
        }

        #pragma unroll
        for (int p = 0; p < 8; p++) {
            float lo, hi;
            unpack2(acc[p], lo, hi);
            Y[(base + 2 * p + 0) * HH + t] = lo;
            Y[(base + 2 * p + 1) * HH + t] = hi;
        }
        __syncthreads();
    }
}

// ---------------------------------------------------------------------------
// One warp per destination row: OUT[r] = [relu]( b + dinv[r]^2*XW[r] + sum norm*XW[col] )
__global__ void __launch_bounds__(256) k_aggregate(const float4* __restrict__ XW,
                                                   const float4* __restrict__ b4,
                                                   float4* __restrict__ OUT,
                                                   int relu) {
    int r = blockIdx.x * (blockDim.x >> 5) + (threadIdx.x >> 5);
    if (r >= NN) return;
    int lane = threadIdx.x & 31;

    float dr = g_dinv[r];
    float s = dr * dr;
    float4 xv = XW[r * 32 + lane];
    float4 bb = b4[lane];
    float4 acc = make_float4(fmaf(s, xv.x, bb.x), fmaf(s, xv.y, bb.y),
                             fmaf(s, xv.z, bb.z), fmaf(s, xv.w, bb.w));

    int j = g_rowptr[r];
    const int end = g_rowptr[r + 1];
    if (j < end) {
        int2 e0 = g_edges[j];
        for (++j; j <= end; ++j) {
            int2 en;
            if (j < end) en = g_edges[j];       // prefetch next edge record
            float4 v = XW[e0.x * 32 + lane];
            float nrm = __int_as_float(e0.y);
            acc.x = fmaf(nrm, v.x, acc.x);
            acc.y = fmaf(nrm, v.y, acc.y);
            acc.z = fmaf(nrm, v.z, acc.z);
            acc.w = fmaf(nrm, v.w, acc.w);
            e0 = en;
        }
    }
    if (relu) {
        acc.x = fmaxf(acc.x, 0.f); acc.y = fmaxf(acc.y, 0.f);
        acc.z = fmaxf(acc.z, 0.f); acc.w = fmaxf(acc.w, 0.f);
    }
    OUT[r * 32 + lane] = acc;
}

// ---------------------------------------------------------------------------
extern "C" void kernel_launch(void* const* d_in, const int* in_sizes, int n_in,
                              void* d_out, int out_size) {
    const float* x   = (const float*)d_in[0];
    const int*   ei  = (const int*)d_in[1];     // [2, E] row-major
    const float* W1  = (const float*)d_in[2];
    const float* b1  = (const float*)d_in[3];
    const float* W2  = (const float*)d_in[4];
    const float* b2  = (const float*)d_in[5];
    float*       out = (float*)d_out;

    const int n = NN, e = EE;
    const int* rows = ei;
    const int* cols = ei + e;

    float* xw; cudaGetSymbolAddress((void**)&xw, g_xw);
    float* h;  cudaGetSymbolAddress((void**)&h,  g_h);

    // --- normalization + CSR build (graph shared by both layers) ---
    k_init<<<(n + 255) / 256, 256>>>(n);
    k_count_deg<<<(e + 255) / 256, 256>>>(rows, e);
    k_scan_blocks<<<SCAN_NB, 256>>>();   // also computes dinv
    k_scan_tops<<<1, 256>>>();
    k_scan_write<<<SCAN_NB, 256>>>();
    k_fill<<<(e + 255) / 256, 256>>>(rows, cols, e);

    const int gemm_blocks = 148 * 4;
    const int agg_blocks  = (n + 7) / 8;   // 8 warps (rows) per 256-thread block

    // --- layer 1 ---
    k_gemm128<<<gemm_blocks, 128>>>(x, W1, xw);
    k_aggregate<<<agg_blocks, 256>>>((const float4*)xw, (const float4*)b1, (float4*)h, 1);

    // --- layer 2 ---
    k_gemm128<<<gemm_blocks, 128>>>(h, W2, xw);
    k_aggregate<<<agg_blocks, 256>>>((const float4*)xw, (const float4*)b2, (float4*)out, 0);
}

// round 11
// speedup vs baseline: 1.9453x; 1.1385x over previous
#include <cuda_runtime.h>
#include <cuda_bf16.h>

// Problem constants (fixed by the reference)
#define NN 50000
#define EE 800000
#define HH 128
#define SCAN_NB 196   // ceil(NN/256)

// Scratch (no cudaMalloc allowed)
__device__ int    g_deg[NN];            // in-degree (no self loop)
__device__ float  g_dinv[NN];
__device__ int    g_rowptr[NN + 1];
__device__ int    g_fill[NN];
__device__ int    g_bsum[256];          // per-block sums (padded)
__device__ int2   g_edges[EE];          // {col, __float_as_int(norm)} grouped by row
__device__ float  g_xw[NN * HH];        // X @ W
__device__ float  g_h[NN * HH];         // hidden activations
__device__ float4 g_wf1[16 * 16 * 32];  // W1 tf32 big/small fragments (per-lane layout)
__device__ float4 g_wf2[16 * 16 * 32];  // W2 fragments

// ---------------------------------------------------------------------------
__device__ __forceinline__ unsigned tf32u(float f) {
    unsigned r;
    asm("cvt.rna.tf32.f32 %0, %1;" : "=r"(r) : "f"(f));
    return r;
}

// D += A(16x8) * B(8x8), tf32 operands, fp32 accumulate
__device__ __forceinline__ void mma8(float* c, const unsigned* a, unsigned b0, unsigned b1) {
    asm("mma.sync.aligned.m16n8k8.row.col.f32.tf32.tf32.f32 "
        "{%0,%1,%2,%3},{%4,%5,%6,%7},{%8,%9},{%0,%1,%2,%3};"
        : "+f"(c[0]), "+f"(c[1]), "+f"(c[2]), "+f"(c[3])
        : "r"(a[0]), "r"(a[1]), "r"(a[2]), "r"(a[3]), "r"(b0), "r"(b1));
}

// ---------------------------------------------------------------------------
__global__ void k_init(int n) {
    int i = blockIdx.x * blockDim.x + threadIdx.x;
    if (i < n) { g_deg[i] = 0; g_fill[i] = 0; }
}

__global__ void k_count_deg(const int* __restrict__ rows, int e) {
    int i = blockIdx.x * blockDim.x + threadIdx.x;
    if (i < e) atomicAdd(&g_deg[rows[i]], 1);
}

// Scan phase 1: per-block sum of deg; also computes dinv = rsqrt(deg+1) (fused).
__global__ void __launch_bounds__(256) k_scan_blocks() {
    __shared__ int ws[8];
    int i = blockIdx.x * 256 + threadIdx.x;
    int v = 0;
    if (i < NN) {
        int d = g_deg[i];
        g_dinv[i] = rsqrtf((float)(d + 1));
        v = d;
    }
    int s = v;
    #pragma unroll
    for (int o = 1; o < 32; o <<= 1) {
        int t = __shfl_up_sync(0xffffffffu, s, o);
        if ((threadIdx.x & 31) >= o) s += t;
    }
    if ((threadIdx.x & 31) == 31) ws[threadIdx.x >> 5] = s;
    __syncthreads();
    if (threadIdx.x == 0) {
        int tot = 0;
        #pragma unroll
        for (int w = 0; w < 8; w++) tot += ws[w];
        g_bsum[blockIdx.x] = tot;
    }
}

// Scan phase 2 (fused tops): each block computes its own base = sum of preceding
// block sums (<=196 ints), then the in-block exclusive scan -> rowptr.
__global__ void __launch_bounds__(256) k_scan_write() {
    __shared__ int ws[8];
    __shared__ int ws2[8];
    __shared__ int base_s;
    const int tid = threadIdx.x;

    // base = sum_{t < blockIdx.x} g_bsum[t]
    int bv = (tid < blockIdx.x) ? g_bsum[tid] : 0;   // blockIdx.x <= 196 < 256
    #pragma unroll
    for (int o = 16; o > 0; o >>= 1) bv += __shfl_down_sync(0xffffffffu, bv, o);
    if ((tid & 31) == 0) ws2[tid >> 5] = bv;
    __syncthreads();
    if (tid == 0) {
        int b = 0;
        #pragma unroll
        for (int w = 0; w < 8; w++) b += ws2[w];
        base_s = b;
        if (blockIdx.x == 0) g_rowptr[NN] = EE;
    }

    int i = blockIdx.x * 256 + tid;
    int v = (i < NN) ? g_deg[i] : 0;
    int s = v;
    #pragma unroll
    for (int o = 1; o < 32; o <<= 1) {
        int t = __shfl_up_sync(0xffffffffu, s, o);
        if ((tid & 31) >= o) s += t;
    }
    if ((tid & 31) == 31) ws[tid >> 5] = s;
    __syncthreads();
    int woff = 0;
    #pragma unroll
    for (int w = 0; w < 8; w++) {
        if (w < (tid >> 5)) woff += ws[w];
    }
    if (i < NN) g_rowptr[i] = base_s + woff + s - v;
}

// Bucket edges by destination row; store {col, norm} per slot.
__global__ void k_fill(const int* __restrict__ rows, const int* __restrict__ cols, int e) {
    int i = blockIdx.x * blockDim.x + threadIdx.x;
    if (i < e) {
        int r = rows[i];
        int c = cols[i];
        int pos = g_rowptr[r] + atomicAdd(&g_fill[r], 1);
        float nrm = g_dinv[r] * g_dinv[c];
        g_edges[pos] = make_int2(c, __float_as_int(nrm));
    }
}

// ---------------------------------------------------------------------------
// Precompute W fragments in exact mma per-lane layout, tf32 big/small packed.
// For (ks, nt, lane): tg=lane%4, gid=lane/4; b0 = W[ks*8+tg][nt*8+gid],
// b1 = W[ks*8+tg+4][nt*8+gid].  F[idx] = {big(b0), big(b1), small(b0), small(b1)}.
__global__ void k_wfrag(const float* __restrict__ W, float4* __restrict__ F) {
    int idx = blockIdx.x * 256 + threadIdx.x;     // 16*16*32 = 8192
    if (idx >= 8192) return;
    int lane = idx & 31, nt = (idx >> 5) & 15, ks = idx >> 9;
    int tg = lane & 3, gid = lane >> 2;
    int n = nt * 8 + gid;
    int k0 = ks * 8 + tg;
    float w0 = W[k0 * HH + n];
    float w1 = W[(k0 + 4) * HH + n];
    unsigned b0 = tf32u(w0);
    unsigned b1 = tf32u(w1);
    unsigned s0 = tf32u(w0 - __uint_as_float(b0));
    unsigned s1 = tf32u(w1 - __uint_as_float(b1));
    F[idx] = make_float4(__uint_as_float(b0), __uint_as_float(b1),
                         __uint_as_float(s0), __uint_as_float(s1));
}

// ---------------------------------------------------------------------------
// Y[NN,128] = X[NN,128] @ W[128,128] via 3xTF32 tensor-core mma.
// Block: 256 thr = 8 warps; tile 64 rows x 128 cols.
// Warp (wm = w%4, wn = w/4): rows [wm*16, +16), cols [wn*64, +64) = 8 n-tiles.
__global__ void __launch_bounds__(256) k_gemm_tc(const float* __restrict__ X,
                                                 const float4* __restrict__ WF,
                                                 float* __restrict__ Y) {
    __shared__ float xs[64 * 132];     // fp32 X tile, stride 132 (conflict-free A reads)
    const int tid = threadIdx.x;
    const int w = tid >> 5, lane = tid & 31;
    const int tg = lane & 3, gid = lane >> 2;
    const int wm = w & 3, wn = w >> 2;
    const int NT = (NN + 63) / 64;     // 782

    for (int tile = blockIdx.x; tile < NT; tile += gridDim.x) {
        const int rb = tile * 64;

        // Load X tile (coalesced float4), zero-pad beyond NN.
        for (int i = tid; i < 64 * 32; i += 256) {
            int row = i >> 5, c4 = i & 31;
            float4 v = (rb + row < NN) ? ((const float4*)X)[(rb + row) * 32 + c4]
                                       : make_float4(0.f, 0.f, 0.f, 0.f);
            *(float4*)&xs[row * 132 + c4 * 4] = v;
        }
        __syncthreads();

        float acc[8][4] = {};
        const int r0 = wm * 16 + gid;

        #pragma unroll 4
        for (int ks = 0; ks < 16; ks++) {
            const int k = ks * 8 + tg;
            float af0 = xs[r0 * 132 + k];
            float af1 = xs[(r0 + 8) * 132 + k];
            float af2 = xs[r0 * 132 + k + 4];
            float af3 = xs[(r0 + 8) * 132 + k + 4];
            unsigned ab[4], as_[4];
            ab[0] = tf32u(af0); as_[0] = tf32u(af0 - __uint_as_float(ab[0]));
            ab[1] = tf32u(af1); as_[1] = tf32u(af1 - __uint_as_float(ab[1]));
            ab[2] = tf32u(af2); as_[2] = tf32u(af2 - __uint_as_float(ab[2]));
            ab[3] = tf32u(af3); as_[3] = tf32u(af3 - __uint_as_float(ab[3]));

            #pragma unroll
            for (int nt = 0; nt < 8; nt++) {
                float4 wf = WF[((ks << 4) + (wn << 3) + nt) * 32 + lane];
                unsigned bb0 = __float_as_uint(wf.x), bb1 = __float_as_uint(wf.y);
                unsigned bs0 = __float_as_uint(wf.z), bs1 = __float_as_uint(wf.w);
                mma8(acc[nt], ab, bb0, bb1);    // big*big
                mma8(acc[nt], ab, bs0, bs1);    // big*small
                mma8(acc[nt], as_, bb0, bb1);   // small*big
            }
        }

        // Epilogue: c0=[gid][2tg], c1=[gid][2tg+1], c2=[gid+8][2tg], c3=[gid+8][2tg+1]
        const int grow0 = rb + r0;
        const int grow1 = grow0 + 8;
        #pragma unroll
        for (int nt = 0; nt < 8; nt++) {
            int col = wn * 64 + nt * 8 + tg * 2;
            if (grow0 < NN) *(float2*)&Y[grow0 * HH + col] = make_float2(acc[nt][0], acc[nt][1]);
            if (grow1 < NN) *(float2*)&Y[grow1 * HH + col] = make_float2(acc[nt][2], acc[nt][3]);
        }
        __syncthreads();
    }
}

// ---------------------------------------------------------------------------
// One warp per destination row: OUT[r] = [relu]( b + dinv[r]^2*XW[r] + sum norm*XW[col] )
__global__ void __launch_bounds__(256) k_aggregate(const float4* __restrict__ XW,
                                                   const float4* __restrict__ b4,
                                                   float4* __restrict__ OUT,
                                                   int relu) {
    int r = blockIdx.x * (blockDim.x >> 5) + (threadIdx.x >> 5);
    if (r >= NN) return;
    int lane = threadIdx.x & 31;

    float dr = g_dinv[r];
    float s = dr * dr;
    float4 xv = XW[r * 32 + lane];
    float4 bb = b4[lane];
    float4 acc = make_float4(fmaf(s, xv.x, bb.x), fmaf(s, xv.y, bb.y),
                             fmaf(s, xv.z, bb.z), fmaf(s, xv.w, bb.w));

    int j = g_rowptr[r];
    const int end = g_rowptr[r + 1];
    if (j < end) {
        int2 e0 = g_edges[j];
        for (++j; j <= end; ++j) {
            int2 en;
            if (j < end) en = g_edges[j];       // prefetch next edge record
            float4 v = XW[e0.x * 32 + lane];
            float nrm = __int_as_float(e0.y);
            acc.x = fmaf(nrm, v.x, acc.x);
            acc.y = fmaf(nrm, v.y, acc.y);
            acc.z = fmaf(nrm, v.z, acc.z);
            acc.w = fmaf(nrm, v.w, acc.w);
            e0 = en;
        }
    }
    if (relu) {
        acc.x = fmaxf(acc.x, 0.f); acc.y = fmaxf(acc.y, 0.f);
        acc.z = fmaxf(acc.z, 0.f); acc.w = fmaxf(acc.w, 0.f);
    }
    OUT[r * 32 + lane] = acc;
}

// ---------------------------------------------------------------------------
extern "C" void kernel_launch(void* const* d_in, const int* in_sizes, int n_in,
                              void* d_out, int out_size) {
    const float* x   = (const float*)d_in[0];
    const int*   ei  = (const int*)d_in[1];     // [2, E] row-major
    const float* W1  = (const float*)d_in[2];
    const float* b1  = (const float*)d_in[3];
    const float* W2  = (const float*)d_in[4];
    const float* b2  = (const float*)d_in[5];
    float*       out = (float*)d_out;

    const int n = NN, e = EE;
    const int* rows = ei;
    const int* cols = ei + e;

    float*  xw;  cudaGetSymbolAddress((void**)&xw,  g_xw);
    float*  h;   cudaGetSymbolAddress((void**)&h,   g_h);
    float4* wf1; cudaGetSymbolAddress((void**)&wf1, g_wf1);
    float4* wf2; cudaGetSymbolAddress((void**)&wf2, g_wf2);

    // --- normalization + CSR build (graph shared by both layers) ---
    k_init<<<(n + 255) / 256, 256>>>(n);
    k_count_deg<<<(e + 255) / 256, 256>>>(rows, e);
    k_scan_blocks<<<SCAN_NB, 256>>>();   // also computes dinv
    k_scan_write<<<SCAN_NB, 256>>>();    // fused tops + write
    k_fill<<<(e + 255) / 256, 256>>>(rows, cols, e);

    // --- W fragment precompute (tf32 big/small, per-lane layout) ---
    k_wfrag<<<32, 256>>>(W1, wf1);
    k_wfrag<<<32, 256>>>(W2, wf2);

    const int gemm_blocks = (n + 63) / 64;   // 782
    const int agg_blocks  = (n + 7) / 8;     // 8 warps (rows) per 256-thread block

    // --- layer 1 ---
    k_gemm_tc<<<gemm_blocks, 256>>>(x, wf1, xw);
    k_aggregate<<<agg_blocks, 256>>>((const float4*)xw, (const float4*)b1, (float4*)h, 1);

    // --- layer 2 ---
    k_gemm_tc<<<gemm_blocks, 256>>>(h, wf2, xw);
    k_aggregate<<<agg_blocks, 256>>>((const float4*)xw, (const float4*)b2, (float4*)out, 0);
}

// round 13
// speedup vs baseline: 2.0935x; 1.0762x over previous
#include <cuda_runtime.h>
#include <cuda_bf16.h>
#include <cuda_fp16.h>

// Problem constants (fixed by the reference)
#define NN 50000
#define EE 800000
#define HH 128
#define SCAN_NB 196   // ceil(NN/256)

// Scratch (no cudaMalloc allowed)
__device__ int     g_deg[NN];            // in-degree (no self loop)
__device__ float   g_dinv[NN];
__device__ int     g_rowptr[NN + 1];
__device__ int     g_fill[NN];
__device__ int     g_bsum[256];          // per-block sums (padded)
__device__ int2    g_edges[EE];          // {col, __float_as_int(norm)} grouped by row
__device__ __half2 g_xwh[NN * 64];       // X @ W in fp16 (gather operand)
__device__ float   g_h[NN * HH];         // hidden activations (fp32)
__device__ float4  g_wf1[16 * 16 * 32];  // W1 tf32 big/small fragments (per-lane layout)
__device__ float4  g_wf2[16 * 16 * 32];  // W2 fragments

// ---------------------------------------------------------------------------
__device__ __forceinline__ unsigned tf32u(float f) {
    unsigned r;
    asm("cvt.rna.tf32.f32 %0, %1;" : "=r"(r) : "f"(f));
    return r;
}

// D += A(16x8) * B(8x8), tf32 operands, fp32 accumulate
__device__ __forceinline__ void mma8(float* c, const unsigned* a, unsigned b0, unsigned b1) {
    asm("mma.sync.aligned.m16n8k8.row.col.f32.tf32.tf32.f32 "
        "{%0,%1,%2,%3},{%4,%5,%6,%7},{%8,%9},{%0,%1,%2,%3};"
        : "+f"(c[0]), "+f"(c[1]), "+f"(c[2]), "+f"(c[3])
        : "r"(a[0]), "r"(a[1]), "r"(a[2]), "r"(a[3]), "r"(b0), "r"(b1));
}

// ---------------------------------------------------------------------------
__global__ void k_init(int n) {
    int i = blockIdx.x * blockDim.x + threadIdx.x;
    if (i < n) g_deg[i] = 0;
}

__global__ void k_count_deg(const int* __restrict__ rows, int e) {
    int i = blockIdx.x * blockDim.x + threadIdx.x;
    if (i < e) atomicAdd(&g_deg[rows[i]], 1);
}

// Scan phase 1: per-block sum of deg; also computes dinv = rsqrt(deg+1) (fused).
__global__ void __launch_bounds__(256) k_scan_blocks() {
    __shared__ int ws[8];
    int i = blockIdx.x * 256 + threadIdx.x;
    int v = 0;
    if (i < NN) {
        int d = g_deg[i];
        g_dinv[i] = rsqrtf((float)(d + 1));
        v = d;
    }
    int s = v;
    #pragma unroll
    for (int o = 1; o < 32; o <<= 1) {
        int t = __shfl_up_sync(0xffffffffu, s, o);
        if ((threadIdx.x & 31) >= o) s += t;
    }
    if ((threadIdx.x & 31) == 31) ws[threadIdx.x >> 5] = s;
    __syncthreads();
    if (threadIdx.x == 0) {
        int tot = 0;
        #pragma unroll
        for (int w = 0; w < 8; w++) tot += ws[w];
        g_bsum[blockIdx.x] = tot;
    }
}

// Scan phase 2 (fused tops): each block computes its own base = sum of preceding
// block sums, then the in-block exclusive scan -> rowptr. Also zeroes g_fill.
__global__ void __launch_bounds__(256) k_scan_write() {
    __shared__ int ws[8];
    __shared__ int ws2[8];
    __shared__ int base_s;
    const int tid = threadIdx.x;

    int bv = (tid < blockIdx.x) ? g_bsum[tid] : 0;   // blockIdx.x <= 196 < 256
    #pragma unroll
    for (int o = 16; o > 0; o >>= 1) bv += __shfl_down_sync(0xffffffffu, bv, o);
    if ((tid & 31) == 0) ws2[tid >> 5] = bv;
    __syncthreads();
    if (tid == 0) {
        int b = 0;
        #pragma unroll
        for (int w = 0; w < 8; w++) b += ws2[w];
        base_s = b;
        if (blockIdx.x == 0) g_rowptr[NN] = EE;
    }

    int i = blockIdx.x * 256 + tid;
    int v = (i < NN) ? g_deg[i] : 0;
    int s = v;
    #pragma unroll
    for (int o = 1; o < 32; o <<= 1) {
        int t = __shfl_up_sync(0xffffffffu, s, o);
        if ((tid & 31) >= o) s += t;
    }
    if ((tid & 31) == 31) ws[tid >> 5] = s;
    __syncthreads();
    int woff = 0;
    #pragma unroll
    for (int w = 0; w < 8; w++) {
        if (w < (tid >> 5)) woff += ws[w];
    }
    if (i < NN) {
        g_rowptr[i] = base_s + woff + s - v;
        g_fill[i] = 0;
    }
}

// Bucket edges by destination row; store {col, norm} per slot.
__global__ void k_fill(const int* __restrict__ rows, const int* __restrict__ cols, int e) {
    int i = blockIdx.x * blockDim.x + threadIdx.x;
    if (i < e) {
        int r = rows[i];
        int c = cols[i];
        int pos = g_rowptr[r] + atomicAdd(&g_fill[r], 1);
        float nrm = g_dinv[r] * g_dinv[c];
        g_edges[pos] = make_int2(c, __float_as_int(nrm));
    }
}

// ---------------------------------------------------------------------------
// Precompute W fragments in exact mma per-lane layout, tf32 big/small packed.
__global__ void k_wfrag(const float* __restrict__ W, float4* __restrict__ F) {
    int idx = blockIdx.x * 256 + threadIdx.x;     // 16*16*32 = 8192
    if (idx >= 8192) return;
    int lane = idx & 31, nt = (idx >> 5) & 15, ks = idx >> 9;
    int tg = lane & 3, gid = lane >> 2;
    int n = nt * 8 + gid;
    int k0 = ks * 8 + tg;
    float w0 = W[k0 * HH + n];
    float w1 = W[(k0 + 4) * HH + n];
    unsigned b0 = tf32u(w0);
    unsigned b1 = tf32u(w1);
    unsigned s0 = tf32u(w0 - __uint_as_float(b0));
    unsigned s1 = tf32u(w1 - __uint_as_float(b1));
    F[idx] = make_float4(__uint_as_float(b0), __uint_as_float(b1),
                         __uint_as_float(s0), __uint_as_float(s1));
}

// ---------------------------------------------------------------------------
// XWH[NN,64 half2] = X[NN,128] @ W[128,128] via 3xTF32 mma, fp16 output.
// Block: 256 thr = 8 warps; tile 64 rows x 128 cols.
__global__ void __launch_bounds__(256) k_gemm_tc(const float* __restrict__ X,
                                                 const float4* __restrict__ WF,
                                                 __half2* __restrict__ Yh) {
    __shared__ float xs[64 * 132];     // fp32 X tile, stride 132 (conflict-free A reads)
    const int tid = threadIdx.x;
    const int w = tid >> 5, lane = tid & 31;
    const int tg = lane & 3, gid = lane >> 2;
    const int wm = w & 3, wn = w >> 2;
    const int NT = (NN + 63) / 64;     // 782

    for (int tile = blockIdx.x; tile < NT; tile += gridDim.x) {
        const int rb = tile * 64;

        for (int i = tid; i < 64 * 32; i += 256) {
            int row = i >> 5, c4 = i & 31;
            float4 v = (rb + row < NN) ? ((const float4*)X)[(rb + row) * 32 + c4]
                                       : make_float4(0.f, 0.f, 0.f, 0.f);
            *(float4*)&xs[row * 132 + c4 * 4] = v;
        }
        __syncthreads();

        float acc[8][4] = {};
        const int r0 = wm * 16 + gid;

        #pragma unroll 4
        for (int ks = 0; ks < 16; ks++) {
            const int k = ks * 8 + tg;
            float af0 = xs[r0 * 132 + k];
            float af1 = xs[(r0 + 8) * 132 + k];
            float af2 = xs[r0 * 132 + k + 4];
            float af3 = xs[(r0 + 8) * 132 + k + 4];
            unsigned ab[4], as_[4];
            ab[0] = tf32u(af0); as_[0] = tf32u(af0 - __uint_as_float(ab[0]));
            ab[1] = tf32u(af1); as_[1] = tf32u(af1 - __uint_as_float(ab[1]));
            ab[2] = tf32u(af2); as_[2] = tf32u(af2 - __uint_as_float(ab[2]));
            ab[3] = tf32u(af3); as_[3] = tf32u(af3 - __uint_as_float(ab[3]));

            #pragma unroll
            for (int nt = 0; nt < 8; nt++) {
                float4 wf = WF[((ks << 4) + (wn << 3) + nt) * 32 + lane];
                unsigned bb0 = __float_as_uint(wf.x), bb1 = __float_as_uint(wf.y);
                unsigned bs0 = __float_as_uint(wf.z), bs1 = __float_as_uint(wf.w);
                mma8(acc[nt], ab, bb0, bb1);    // big*big
                mma8(acc[nt], ab, bs0, bs1);    // big*small
                mma8(acc[nt], as_, bb0, bb1);   // small*big
            }
        }

        // Epilogue: pair (c0,c1) -> half2 at row gid, (c2,c3) -> row gid+8.
        const int grow0 = rb + r0;
        const int grow1 = grow0 + 8;
        #pragma unroll
        for (int nt = 0; nt < 8; nt++) {
            int c2 = wn * 32 + nt * 4 + tg;    // half2 index within the 64-wide row
            if (grow0 < NN) Yh[grow0 * 64 + c2] = __floats2half2_rn(acc[nt][0], acc[nt][1]);
            if (grow1 < NN) Yh[grow1 * 64 + c2] = __floats2half2_rn(acc[nt][2], acc[nt][3]);
        }
        __syncthreads();
    }
}

// ---------------------------------------------------------------------------
// One warp per destination row, fp16 gather / fp32 accumulate:
// OUT[r] = [relu]( b + dinv[r]^2*XWH[r] + sum norm*XWH[col] )
// Lane covers cols [4*lane, 4*lane+4): one uint2 = 2 x half2 per row.
__global__ void __launch_bounds__(256) k_aggregate(const uint2* __restrict__ XWH,
                                                   const float4* __restrict__ b4,
                                                   float4* __restrict__ OUT,
                                                   int relu) {
    int r = blockIdx.x * (blockDim.x >> 5) + (threadIdx.x >> 5);
    if (r >= NN) return;
    int lane = threadIdx.x & 31;

    float dr = g_dinv[r];
    float s = dr * dr;
    uint2 xp = XWH[r * 32 + lane];
    float2 x0 = __half22float2(*(const __half2*)&xp.x);
    float2 x1 = __half22float2(*(const __half2*)&xp.y);
    float4 bb = b4[lane];
    float4 acc = make_float4(fmaf(s, x0.x, bb.x), fmaf(s, x0.y, bb.y),
                             fmaf(s, x1.x, bb.z), fmaf(s, x1.y, bb.w));

    int j = g_rowptr[r];
    const int end = g_rowptr[r + 1];
    if (j < end) {
        int2 e0 = g_edges[j];
        for (++j; j <= end; ++j) {
            int2 en;
            if (j < end) en = g_edges[j];       // prefetch next edge record
            uint2 p = XWH[e0.x * 32 + lane];
            float nrm = __int_as_float(e0.y);
            float2 v0 = __half22float2(*(const __half2*)&p.x);
            float2 v1 = __half22float2(*(const __half2*)&p.y);
            acc.x = fmaf(nrm, v0.x, acc.x);
            acc.y = fmaf(nrm, v0.y, acc.y);
            acc.z = fmaf(nrm, v1.x, acc.z);
            acc.w = fmaf(nrm, v1.y, acc.w);
            e0 = en;
        }
    }
    if (relu) {
        acc.x = fmaxf(acc.x, 0.f); acc.y = fmaxf(acc.y, 0.f);
        acc.z = fmaxf(acc.z, 0.f); acc.w = fmaxf(acc.w, 0.f);
    }
    OUT[r * 32 + lane] = acc;
}

// ---------------------------------------------------------------------------
extern "C" void kernel_launch(void* const* d_in, const int* in_sizes, int n_in,
                              void* d_out, int out_size) {
    const float* x   = (const float*)d_in[0];
    const int*   ei  = (const int*)d_in[1];     // [2, E] row-major
    const float* W1  = (const float*)d_in[2];
    const float* b1  = (const float*)d_in[3];
    const float* W2  = (const float*)d_in[4];
    const float* b2  = (const float*)d_in[5];
    float*       out = (float*)d_out;

    const int n = NN, e = EE;
    const int* rows = ei;
    const int* cols = ei + e;

    __half2* xwh; cudaGetSymbolAddress((void**)&xwh, g_xwh);
    float*   h;   cudaGetSymbolAddress((void**)&h,   g_h);
    float4*  wf1; cudaGetSymbolAddress((void**)&wf1, g_wf1);
    float4*  wf2; cudaGetSymbolAddress((void**)&wf2, g_wf2);

    // --- normalization + CSR build (graph shared by both layers) ---
    k_init<<<(n + 255) / 256, 256>>>(n);
    k_count_deg<<<(e + 255) / 256, 256>>>(rows, e);
    k_scan_blocks<<<SCAN_NB, 256>>>();   // also computes dinv
    k_scan_write<<<SCAN_NB, 256>>>();    // fused tops + write, zeroes g_fill
    k_fill<<<(e + 255) / 256, 256>>>(rows, cols, e);

    // --- W fragment precompute (tf32 big/small, per-lane layout) ---
    k_wfrag<<<32, 256>>>(W1, wf1);
    k_wfrag<<<32, 256>>>(W2, wf2);

    const int gemm_blocks = (n + 63) / 64;   // 782
    const int agg_blocks  = (n + 7) / 8;     // 8 warps (rows) per 256-thread block

    // --- layer 1 ---
    k_gemm_tc<<<gemm_blocks, 256>>>(x, wf1, xwh);
    k_aggregate<<<agg_blocks, 256>>>((const uint2*)xwh, (const float4*)b1, (float4*)h, 1);

    // --- layer 2 ---
    k_gemm_tc<<<gemm_blocks, 256>>>(h, wf2, xwh);
    k_aggregate<<<agg_blocks, 256>>>((const uint2*)xwh, (const float4*)b2, (float4*)out, 0);
}

// round 14
// speedup vs baseline: 2.2348x; 1.0675x over previous
#include <cuda_runtime.h>
#include <cuda_bf16.h>
#include <cuda_fp16.h>

// Problem constants (fixed by the reference)
#define NN 50000
#define EE 800000
#define HH 128
#define SCAN_NB 196   // ceil(NN/256)

// Scratch (no cudaMalloc allowed)
__device__ int      g_deg[NN];            // in-degree (no self loop)
__device__ float    g_dinv[NN];
__device__ int      g_rowptr[NN + 1];
__device__ int      g_fill[NN];
__device__ int      g_bsum[256];          // per-block sums (padded)
__device__ unsigned g_edgesp[EE];         // packed {col:u16 | half(norm)<<16}, grouped by row
__device__ __half2  g_xwh[NN * 64];       // X @ W in fp16 (gather operand)
__device__ float    g_h[NN * HH];         // hidden activations (fp32)
__device__ float4   g_wf1[16 * 16 * 32];  // W1 tf32 big/small fragments (per-lane layout)
__device__ float4   g_wf2[16 * 16 * 32];  // W2 fragments

// ---------------------------------------------------------------------------
__device__ __forceinline__ unsigned tf32u(float f) {
    unsigned r;
    asm("cvt.rna.tf32.f32 %0, %1;" : "=r"(r) : "f"(f));
    return r;
}

// D += A(16x8) * B(8x8), tf32 operands, fp32 accumulate
__device__ __forceinline__ void mma8(float* c, const unsigned* a, unsigned b0, unsigned b1) {
    asm("mma.sync.aligned.m16n8k8.row.col.f32.tf32.tf32.f32 "
        "{%0,%1,%2,%3},{%4,%5,%6,%7},{%8,%9},{%0,%1,%2,%3};"
        : "+f"(c[0]), "+f"(c[1]), "+f"(c[2]), "+f"(c[3])
        : "r"(a[0]), "r"(a[1]), "r"(a[2]), "r"(a[3]), "r"(b0), "r"(b1));
}

// ---------------------------------------------------------------------------
// Fused setup: zero deg (threads 0..NN-1) + W1/W2 fragment precompute
// (threads NN..NN+16383). Fragment layout: for (ks, nt, lane): tg=lane%4,
// gid=lane/4; b0=W[ks*8+tg][nt*8+gid], b1=W[ks*8+tg+4][nt*8+gid];
// F = {big(b0), big(b1), small(b0), small(b1)}.
__global__ void k_setup(const float* __restrict__ W1, const float* __restrict__ W2) {
    int i = blockIdx.x * 256 + threadIdx.x;
    if (i < NN) {
        g_deg[i] = 0;
        return;
    }
    int j = i - NN;
    if (j >= 16384) return;
    const float* W = (j < 8192) ? W1 : W2;
    float4* F = (j < 8192) ? g_wf1 : g_wf2;
    int idx = j & 8191;
    int lane = idx & 31, nt = (idx >> 5) & 15, ks = idx >> 9;
    int tg = lane & 3, gid = lane >> 2;
    int n = nt * 8 + gid;
    int k0 = ks * 8 + tg;
    float w0 = W[k0 * HH + n];
    float w1 = W[(k0 + 4) * HH + n];
    unsigned b0 = tf32u(w0);
    unsigned b1 = tf32u(w1);
    unsigned s0 = tf32u(w0 - __uint_as_float(b0));
    unsigned s1 = tf32u(w1 - __uint_as_float(b1));
    F[idx] = make_float4(__uint_as_float(b0), __uint_as_float(b1),
                         __uint_as_float(s0), __uint_as_float(s1));
}

__global__ void k_count_deg(const int* __restrict__ rows, int e) {
    int i = blockIdx.x * blockDim.x + threadIdx.x;
    if (i < e) atomicAdd(&g_deg[rows[i]], 1);
}

// Scan phase 1: per-block sum of deg; also computes dinv = rsqrt(deg+1) (fused).
__global__ void __launch_bounds__(256) k_scan_blocks() {
    __shared__ int ws[8];
    int i = blockIdx.x * 256 + threadIdx.x;
    int v = 0;
    if (i < NN) {
        int d = g_deg[i];
        g_dinv[i] = rsqrtf((float)(d + 1));
        v = d;
    }
    int s = v;
    #pragma unroll
    for (int o = 1; o < 32; o <<= 1) {
        int t = __shfl_up_sync(0xffffffffu, s, o);
        if ((threadIdx.x & 31) >= o) s += t;
    }
    if ((threadIdx.x & 31) == 31) ws[threadIdx.x >> 5] = s;
    __syncthreads();
    if (threadIdx.x == 0) {
        int tot = 0;
        #pragma unroll
        for (int w = 0; w < 8; w++) tot += ws[w];
        g_bsum[blockIdx.x] = tot;
    }
}

// Scan phase 2 (fused tops): each block computes its own base = sum of preceding
// block sums, then the in-block exclusive scan -> rowptr. Also zeroes g_fill.
__global__ void __launch_bounds__(256) k_scan_write() {
    __shared__ int ws[8];
    __shared__ int ws2[8];
    __shared__ int base_s;
    const int tid = threadIdx.x;

    int bv = (tid < blockIdx.x) ? g_bsum[tid] : 0;   // blockIdx.x <= 196 < 256
    #pragma unroll
    for (int o = 16; o > 0; o >>= 1) bv += __shfl_down_sync(0xffffffffu, bv, o);
    if ((tid & 31) == 0) ws2[tid >> 5] = bv;
    __syncthreads();
    if (tid == 0) {
        int b = 0;
        #pragma unroll
        for (int w = 0; w < 8; w++) b += ws2[w];
        base_s = b;
        if (blockIdx.x == 0) g_rowptr[NN] = EE;
    }

    int i = blockIdx.x * 256 + tid;
    int v = (i < NN) ? g_deg[i] : 0;
    int s = v;
    #pragma unroll
    for (int o = 1; o < 32; o <<= 1) {
        int t = __shfl_up_sync(0xffffffffu, s, o);
        if ((tid & 31) >= o) s += t;
    }
    if ((tid & 31) == 31) ws[tid >> 5] = s;
    __syncthreads();
    int woff = 0;
    #pragma unroll
    for (int w = 0; w < 8; w++) {
        if (w < (tid >> 5)) woff += ws[w];
    }
    if (i < NN) {
        g_rowptr[i] = base_s + woff + s - v;
        g_fill[i] = 0;
    }
}

// Bucket edges by destination row; packed 4-byte record {col:u16, norm:f16}.
__global__ void k_fill(const int* __restrict__ rows, const int* __restrict__ cols, int e) {
    int i = blockIdx.x * blockDim.x + threadIdx.x;
    if (i < e) {
        int r = rows[i];
        int c = cols[i];
        int pos = g_rowptr[r] + atomicAdd(&g_fill[r], 1);
        float nrm = g_dinv[r] * g_dinv[c];
        unsigned hn = (unsigned)__half_as_ushort(__float2half_rn(nrm));
        g_edgesp[pos] = (unsigned)c | (hn << 16);
    }
}

// ---------------------------------------------------------------------------
// XWH[NN,64 half2] = X[NN,128] @ W[128,128] via 3xTF32 mma, fp16 output.
// Block: 256 thr = 8 warps; tile 64 rows x 128 cols.
__global__ void __launch_bounds__(256) k_gemm_tc(const float* __restrict__ X,
                                                 const float4* __restrict__ WF,
                                                 __half2* __restrict__ Yh) {
    __shared__ float xs[64 * 132];     // fp32 X tile, stride 132 (conflict-free A reads)
    const int tid = threadIdx.x;
    const int w = tid >> 5, lane = tid & 31;
    const int tg = lane & 3, gid = lane >> 2;
    const int wm = w & 3, wn = w >> 2;
    const int NT = (NN + 63) / 64;     // 782

    for (int tile = blockIdx.x; tile < NT; tile += gridDim.x) {
        const int rb = tile * 64;

        for (int i = tid; i < 64 * 32; i += 256) {
            int row = i >> 5, c4 = i & 31;
            float4 v = (rb + row < NN) ? ((const float4*)X)[(rb + row) * 32 + c4]
                                       : make_float4(0.f, 0.f, 0.f, 0.f);
            *(float4*)&xs[row * 132 + c4 * 4] = v;
        }
        __syncthreads();

        float acc[8][4] = {};
        const int r0 = wm * 16 + gid;

        #pragma unroll 4
        for (int ks = 0; ks < 16; ks++) {
            const int k = ks * 8 + tg;
            float af0 = xs[r0 * 132 + k];
            float af1 = xs[(r0 + 8) * 132 + k];
            float af2 = xs[r0 * 132 + k + 4];
            float af3 = xs[(r0 + 8) * 132 + k + 4];
            unsigned ab[4], as_[4];
            ab[0] = tf32u(af0); as_[0] = tf32u(af0 - __uint_as_float(ab[0]));
            ab[1] = tf32u(af1); as_[1] = tf32u(af1 - __uint_as_float(ab[1]));
            ab[2] = tf32u(af2); as_[2] = tf32u(af2 - __uint_as_float(ab[2]));
            ab[3] = tf32u(af3); as_[3] = tf32u(af3 - __uint_as_float(ab[3]));

            #pragma unroll
            for (int nt = 0; nt < 8; nt++) {
                float4 wf = WF[((ks << 4) + (wn << 3) + nt) * 32 + lane];
                unsigned bb0 = __float_as_uint(wf.x), bb1 = __float_as_uint(wf.y);
                unsigned bs0 = __float_as_uint(wf.z), bs1 = __float_as_uint(wf.w);
                mma8(acc[nt], ab, bb0, bb1);    // big*big
                mma8(acc[nt], ab, bs0, bs1);    // big*small
                mma8(acc[nt], as_, bb0, bb1);   // small*big
            }
        }

        // Epilogue: pair (c0,c1) -> half2 at row gid, (c2,c3) -> row gid+8.
        const int grow0 = rb + r0;
        const int grow1 = grow0 + 8;
        #pragma unroll
        for (int nt = 0; nt < 8; nt++) {
            int c2 = wn * 32 + nt * 4 + tg;    // half2 index within the 64-wide row
            if (grow0 < NN) Yh[grow0 * 64 + c2] = __floats2half2_rn(acc[nt][0], acc[nt][1]);
            if (grow1 < NN) Yh[grow1 * 64 + c2] = __floats2half2_rn(acc[nt][2], acc[nt][3]);
        }
        __syncthreads();
    }
}

// ---------------------------------------------------------------------------
// One warp per destination row, fp16 gather / fp32 accumulate, 2-edge unroll
// (MLP=2 on the feature gathers):
// OUT[r] = [relu]( b + dinv[r]^2*XWH[r] + sum norm*XWH[col] )
__global__ void __launch_bounds__(256) k_aggregate(const uint2* __restrict__ XWH,
                                                   const float4* __restrict__ b4,
                                                   float4* __restrict__ OUT,
                                                   int relu) {
    int r = blockIdx.x * (blockDim.x >> 5) + (threadIdx.x >> 5);
    if (r >= NN) return;
    int lane = threadIdx.x & 31;

    float dr = g_dinv[r];
    float s = dr * dr;
    uint2 xp = XWH[r * 32 + lane];
    float2 x0 = __half22float2(*(const __half2*)&xp.x);
    float2 x1 = __half22float2(*(const __half2*)&xp.y);
    float4 bb = b4[lane];
    float4 acc = make_float4(fmaf(s, x0.x, bb.x), fmaf(s, x0.y, bb.y),
                             fmaf(s, x1.x, bb.z), fmaf(s, x1.y, bb.w));

    int j = g_rowptr[r];
    const int end = g_rowptr[r + 1];

    for (; j + 1 < end; j += 2) {
        unsigned e0 = g_edgesp[j];
        unsigned e1 = g_edgesp[j + 1];
        uint2 p0 = XWH[(e0 & 0xFFFFu) * 32 + lane];   // both gathers in flight
        uint2 p1 = XWH[(e1 & 0xFFFFu) * 32 + lane];
        float n0 = __half2float(__ushort_as_half((unsigned short)(e0 >> 16)));
        float n1 = __half2float(__ushort_as_half((unsigned short)(e1 >> 16)));
        float2 a0 = __half22float2(*(const __half2*)&p0.x);
        float2 a1 = __half22float2(*(const __half2*)&p0.y);
        float2 c0 = __half22float2(*(const __half2*)&p1.x);
        float2 c1 = __half22float2(*(const __half2*)&p1.y);
        acc.x = fmaf(n0, a0.x, acc.x); acc.y = fmaf(n0, a0.y, acc.y);
        acc.z = fmaf(n0, a1.x, acc.z); acc.w = fmaf(n0, a1.y, acc.w);
        acc.x = fmaf(n1, c0.x, acc.x); acc.y = fmaf(n1, c0.y, acc.y);
        acc.z = fmaf(n1, c1.x, acc.z); acc.w = fmaf(n1, c1.y, acc.w);
    }
    if (j < end) {
        unsigned e0 = g_edgesp[j];
        uint2 p0 = XWH[(e0 & 0xFFFFu) * 32 + lane];
        float n0 = __half2float(__ushort_as_half((unsigned short)(e0 >> 16)));
        float2 a0 = __half22float2(*(const __half2*)&p0.x);
        float2 a1 = __half22float2(*(const __half2*)&p0.y);
        acc.x = fmaf(n0, a0.x, acc.x); acc.y = fmaf(n0, a0.y, acc.y);
        acc.z = fmaf(n0, a1.x, acc.z); acc.w = fmaf(n0, a1.y, acc.w);
    }

    if (relu) {
        acc.x = fmaxf(acc.x, 0.f); acc.y = fmaxf(acc.y, 0.f);
        acc.z = fmaxf(acc.z, 0.f); acc.w = fmaxf(acc.w, 0.f);
    }
    OUT[r * 32 + lane] = acc;
}

// ---------------------------------------------------------------------------
extern "C" void kernel_launch(void* const* d_in, const int* in_sizes, int n_in,
                              void* d_out, int out_size) {
    const float* x   = (const float*)d_in[0];
    const int*   ei  = (const int*)d_in[1];     // [2, E] row-major
    const float* W1  = (const float*)d_in[2];
    const float* b1  = (const float*)d_in[3];
    const float* W2  = (const float*)d_in[4];
    const float* b2  = (const float*)d_in[5];
    float*       out = (float*)d_out;

    const int n = NN, e = EE;
    const int* rows = ei;
    const int* cols = ei + e;

    __half2* xwh; cudaGetSymbolAddress((void**)&xwh, g_xwh);
    float*   h;   cudaGetSymbolAddress((void**)&h,   g_h);
    float4*  wf1; cudaGetSymbolAddress((void**)&wf1, g_wf1);
    float4*  wf2; cudaGetSymbolAddress((void**)&wf2, g_wf2);

    // --- fused setup (deg zero + W fragments) ---
    k_setup<<<(n + 16384 + 255) / 256, 256>>>(W1, W2);
    k_count_deg<<<(e + 255) / 256, 256>>>(rows, e);
    k_scan_blocks<<<SCAN_NB, 256>>>();   // also computes dinv
    k_scan_write<<<SCAN_NB, 256>>>();    // fused tops + write, zeroes g_fill
    k_fill<<<(e + 255) / 256, 256>>>(rows, cols, e);

    const int gemm_blocks = (n + 63) / 64;   // 782
    const int agg_blocks  = (n + 7) / 8;     // 8 warps (rows) per 256-thread block

    // --- layer 1 ---
    k_gemm_tc<<<gemm_blocks, 256>>>(x, wf1, xwh);
    k_aggregate<<<agg_blocks, 256>>>((const uint2*)xwh, (const float4*)b1, (float4*)h, 1);

    // --- layer 2 ---
    k_gemm_tc<<<gemm_blocks, 256>>>(h, wf2, xwh);
    k_aggregate<<<agg_blocks, 256>>>((const uint2*)xwh, (const float4*)b2, (float4*)out, 0);
}

// round 16
// speedup vs baseline: 2.2839x; 1.0220x over previous
#include <cuda_runtime.h>
#include <cuda_bf16.h>
#include <cuda_fp16.h>

// Problem constants (fixed by the reference)
#define NN 50000
#define EE 800000
#define HH 128
#define SCAN_NB 196   // ceil(NN/256)

// Scratch (no cudaMalloc allowed)
__device__ int      g_deg[NN];            // in-degree (no self loop)
__device__ float    g_dinv[NN];
__device__ int      g_rowptr[NN + 1];
__device__ int      g_fill[NN];
__device__ int      g_bsum[256];          // per-block sums (padded)
__device__ unsigned g_edgesp[EE];         // packed {col:u16 | half(norm)<<16}, grouped by row
__device__ __half2  g_xwh[NN * 64];       // X @ W in fp16 (gather operand)
__device__ float    g_h[NN * HH];         // hidden activations (fp32)
__device__ float4   g_wf1[16 * 16 * 32];  // W1 tf32 big/small fragments (per-lane layout)
__device__ float4   g_wf2[16 * 16 * 32];  // W2 fragments

// ---------------------------------------------------------------------------
__device__ __forceinline__ unsigned tf32u(float f) {
    unsigned r;
    asm("cvt.rna.tf32.f32 %0, %1;" : "=r"(r) : "f"(f));
    return r;
}

// D += A(16x8) * B(8x8), tf32 operands, fp32 accumulate
__device__ __forceinline__ void mma8(float* c, const unsigned* a, unsigned b0, unsigned b1) {
    asm("mma.sync.aligned.m16n8k8.row.col.f32.tf32.tf32.f32 "
        "{%0,%1,%2,%3},{%4,%5,%6,%7},{%8,%9},{%0,%1,%2,%3};"
        : "+f"(c[0]), "+f"(c[1]), "+f"(c[2]), "+f"(c[3])
        : "r"(a[0]), "r"(a[1]), "r"(a[2]), "r"(a[3]), "r"(b0), "r"(b1));
}

// 8-wide fp32 accumulate of a 16-byte fp16 chunk: acc[i] += n * chunk[i]
__device__ __forceinline__ void fma8h(float* acc, uint4 p, float n) {
    float2 v0 = __half22float2(*(const __half2*)&p.x);
    float2 v1 = __half22float2(*(const __half2*)&p.y);
    float2 v2 = __half22float2(*(const __half2*)&p.z);
    float2 v3 = __half22float2(*(const __half2*)&p.w);
    acc[0] = fmaf(n, v0.x, acc[0]); acc[1] = fmaf(n, v0.y, acc[1]);
    acc[2] = fmaf(n, v1.x, acc[2]); acc[3] = fmaf(n, v1.y, acc[3]);
    acc[4] = fmaf(n, v2.x, acc[4]); acc[5] = fmaf(n, v2.y, acc[5]);
    acc[6] = fmaf(n, v3.x, acc[6]); acc[7] = fmaf(n, v3.y, acc[7]);
}

// ---------------------------------------------------------------------------
// Fused setup: zero deg (threads 0..NN-1) + W1/W2 fragment precompute.
__global__ void k_setup(const float* __restrict__ W1, const float* __restrict__ W2) {
    int i = blockIdx.x * 256 + threadIdx.x;
    if (i < NN) {
        g_deg[i] = 0;
        return;
    }
    int j = i - NN;
    if (j >= 16384) return;
    const float* W = (j < 8192) ? W1 : W2;
    float4* F = (j < 8192) ? g_wf1 : g_wf2;
    int idx = j & 8191;
    int lane = idx & 31, nt = (idx >> 5) & 15, ks = idx >> 9;
    int tg = lane & 3, gid = lane >> 2;
    int n = nt * 8 + gid;
    int k0 = ks * 8 + tg;
    float w0 = W[k0 * HH + n];
    float w1 = W[(k0 + 4) * HH + n];
    unsigned b0 = tf32u(w0);
    unsigned b1 = tf32u(w1);
    unsigned s0 = tf32u(w0 - __uint_as_float(b0));
    unsigned s1 = tf32u(w1 - __uint_as_float(b1));
    F[idx] = make_float4(__uint_as_float(b0), __uint_as_float(b1),
                         __uint_as_float(s0), __uint_as_float(s1));
}

__global__ void k_count_deg(const int* __restrict__ rows, int e) {
    int i = blockIdx.x * blockDim.x + threadIdx.x;
    if (i < e) atomicAdd(&g_deg[rows[i]], 1);
}

// Scan phase 1: per-block sum of deg; also computes dinv = rsqrt(deg+1) (fused).
__global__ void __launch_bounds__(256) k_scan_blocks() {
    __shared__ int ws[8];
    int i = blockIdx.x * 256 + threadIdx.x;
    int v = 0;
    if (i < NN) {
        int d = g_deg[i];
        g_dinv[i] = rsqrtf((float)(d + 1));
        v = d;
    }
    int s = v;
    #pragma unroll
    for (int o = 1; o < 32; o <<= 1) {
        int t = __shfl_up_sync(0xffffffffu, s, o);
        if ((threadIdx.x & 31) >= o) s += t;
    }
    if ((threadIdx.x & 31) == 31) ws[threadIdx.x >> 5] = s;
    __syncthreads();
    if (threadIdx.x == 0) {
        int tot = 0;
        #pragma unroll
        for (int w = 0; w < 8; w++) tot += ws[w];
        g_bsum[blockIdx.x] = tot;
    }
}

// Scan phase 2 (fused tops): base = sum of preceding block sums, then
// in-block exclusive scan -> rowptr. Also zeroes g_fill.
__global__ void __launch_bounds__(256) k_scan_write() {
    __shared__ int ws[8];
    __shared__ int ws2[8];
    __shared__ int base_s;
    const int tid = threadIdx.x;

    int bv = (tid < blockIdx.x) ? g_bsum[tid] : 0;   // blockIdx.x <= 196 < 256
    #pragma unroll
    for (int o = 16; o > 0; o >>= 1) bv += __shfl_down_sync(0xffffffffu, bv, o);
    if ((tid & 31) == 0) ws2[tid >> 5] = bv;
    __syncthreads();
    if (tid == 0) {
        int b = 0;
        #pragma unroll
        for (int w = 0; w < 8; w++) b += ws2[w];
        base_s = b;
        if (blockIdx.x == 0) g_rowptr[NN] = EE;
    }

    int i = blockIdx.x * 256 + tid;
    int v = (i < NN) ? g_deg[i] : 0;
    int s = v;
    #pragma unroll
    for (int o = 1; o < 32; o <<= 1) {
        int t = __shfl_up_sync(0xffffffffu, s, o);
        if ((tid & 31) >= o) s += t;
    }
    if ((tid & 31) == 31) ws[tid >> 5] = s;
    __syncthreads();
    int woff = 0;
    #pragma unroll
    for (int w = 0; w < 8; w++) {
        if (w < (tid >> 5)) woff += ws[w];
    }
    if (i < NN) {
        g_rowptr[i] = base_s + woff + s - v;
        g_fill[i] = 0;
    }
}

// Bucket edges by destination row; packed 4-byte record {col:u16, norm:f16}.
__global__ void k_fill(const int* __restrict__ rows, const int* __restrict__ cols, int e) {
    int i = blockIdx.x * blockDim.x + threadIdx.x;
    if (i < e) {
        int r = rows[i];
        int c = cols[i];
        int pos = g_rowptr[r] + atomicAdd(&g_fill[r], 1);
        float nrm = g_dinv[r] * g_dinv[c];
        unsigned hn = (unsigned)__half_as_ushort(__float2half_rn(nrm));
        g_edgesp[pos] = (unsigned)c | (hn << 16);
    }
}

// ---------------------------------------------------------------------------
// XWH[NN,64 half2] = X[NN,128] @ W[128,128] via 3xTF32 mma, fp16 output.
__global__ void __launch_bounds__(256) k_gemm_tc(const float* __restrict__ X,
                                                 const float4* __restrict__ WF,
                                                 __half2* __restrict__ Yh) {
    __shared__ float xs[64 * 132];     // fp32 X tile, stride 132 (conflict-free A reads)
    const int tid = threadIdx.x;
    const int w = tid >> 5, lane = tid & 31;
    const int tg = lane & 3, gid = lane >> 2;
    const int wm = w & 3, wn = w >> 2;
    const int NT = (NN + 63) / 64;     // 782

    for (int tile = blockIdx.x; tile < NT; tile += gridDim.x) {
        const int rb = tile * 64;

        for (int i = tid; i < 64 * 32; i += 256) {
            int row = i >> 5, c4 = i & 31;
            float4 v = (rb + row < NN) ? ((const float4*)X)[(rb + row) * 32 + c4]
                                       : make_float4(0.f, 0.f, 0.f, 0.f);
            *(float4*)&xs[row * 132 + c4 * 4] = v;
        }
        __syncthreads();

        float acc[8][4] = {};
        const int r0 = wm * 16 + gid;

        #pragma unroll 4
        for (int ks = 0; ks < 16; ks++) {
            const int k = ks * 8 + tg;
            float af0 = xs[r0 * 132 + k];
            float af1 = xs[(r0 + 8) * 132 + k];
            float af2 = xs[r0 * 132 + k + 4];
            float af3 = xs[(r0 + 8) * 132 + k + 4];
            unsigned ab[4], as_[4];
            ab[0] = tf32u(af0); as_[0] = tf32u(af0 - __uint_as_float(ab[0]));
            ab[1] = tf32u(af1); as_[1] = tf32u(af1 - __uint_as_float(ab[1]));
            ab[2] = tf32u(af2); as_[2] = tf32u(af2 - __uint_as_float(ab[2]));
            ab[3] = tf32u(af3); as_[3] = tf32u(af3 - __uint_as_float(ab[3]));

            #pragma unroll
            for (int nt = 0; nt < 8; nt++) {
                float4 wf = WF[((ks << 4) + (wn << 3) + nt) * 32 + lane];
                unsigned bb0 = __float_as_uint(wf.x), bb1 = __float_as_uint(wf.y);
                unsigned bs0 = __float_as_uint(wf.z), bs1 = __float_as_uint(wf.w);
                mma8(acc[nt], ab, bb0, bb1);    // big*big
                mma8(acc[nt], ab, bs0, bs1);    // big*small
                mma8(acc[nt], as_, bb0, bb1);   // small*big
            }
        }

        const int grow0 = rb + r0;
        const int grow1 = grow0 + 8;
        #pragma unroll
        for (int nt = 0; nt < 8; nt++) {
            int c2 = wn * 32 + nt * 4 + tg;    // half2 index within the 64-wide row
            if (grow0 < NN) Yh[grow0 * 64 + c2] = __floats2half2_rn(acc[nt][0], acc[nt][1]);
            if (grow1 < NN) Yh[grow1 * 64 + c2] = __floats2half2_rn(acc[nt][2], acc[nt][3]);
        }
        __syncthreads();
    }
}

// ---------------------------------------------------------------------------
// Half-warp per destination row: 16 lanes x uint4 (LDG.128) cover the 256-byte
// fp16 feature row; 2 rows per warp; 2-edge unroll -> ~4 gathers in flight/warp.
// OUT[r] = [relu]( b + dinv[r]^2*XWH[r] + sum norm*XWH[col] )
__global__ void __launch_bounds__(256) k_aggregate(const uint4* __restrict__ XWH,
                                                   const float4* __restrict__ b4,
                                                   float4* __restrict__ OUT,
                                                   int relu) {
    const int tid = threadIdx.x;
    const int l16 = tid & 15;
    int r = blockIdx.x * 16 + (tid >> 4);     // 16 rows per 256-thread block
    if (r >= NN) return;

    float dr = g_dinv[r];
    float s = dr * dr;
    float acc[8];
    {
        float4 bb0 = b4[l16 * 2];
        float4 bb1 = b4[l16 * 2 + 1];
        acc[0] = bb0.x; acc[1] = bb0.y; acc[2] = bb0.z; acc[3] = bb0.w;
        acc[4] = bb1.x; acc[5] = bb1.y; acc[6] = bb1.z; acc[7] = bb1.w;
        uint4 xp = XWH[r * 16 + l16];
        fma8h(acc, xp, s);
    }

    int j = g_rowptr[r];
    const int end = g_rowptr[r + 1];

    for (; j + 1 < end; j += 2) {
        unsigned e0 = g_edgesp[j];
        unsigned e1 = g_edgesp[j + 1];
        uint4 p0 = XWH[(e0 & 0xFFFFu) * 16 + l16];   // both gathers in flight
        uint4 p1 = XWH[(e1 & 0xFFFFu) * 16 + l16];
        float n0 = __half2float(__ushort_as_half((unsigned short)(e0 >> 16)));
        float n1 = __half2float(__ushort_as_half((unsigned short)(e1 >> 16)));
        fma8h(acc, p0, n0);
        fma8h(acc, p1, n1);
    }
    if (j < end) {
        unsigned e0 = g_edgesp[j];
        uint4 p0 = XWH[(e0 & 0xFFFFu) * 16 + l16];
        float n0 = __half2float(__ushort_as_half((unsigned short)(e0 >> 16)));
        fma8h(acc, p0, n0);
    }

    if (relu) {
        #pragma unroll
        for (int i = 0; i < 8; i++) acc[i] = fmaxf(acc[i], 0.f);
    }
    OUT[r * 32 + l16 * 2]     = make_float4(acc[0], acc[1], acc[2], acc[3]);
    OUT[r * 32 + l16 * 2 + 1] = make_float4(acc[4], acc[5], acc[6], acc[7]);
}

// ---------------------------------------------------------------------------
extern "C" void kernel_launch(void* const* d_in, const int* in_sizes, int n_in,
                              void* d_out, int out_size) {
    const float* x   = (const float*)d_in[0];
    const int*   ei  = (const int*)d_in[1];     // [2, E] row-major
    const float* W1  = (const float*)d_in[2];
    const float* b1  = (const float*)d_in[3];
    const float* W2  = (const float*)d_in[4];
    const float* b2  = (const float*)d_in[5];
    float*       out = (float*)d_out;

    const int n = NN, e = EE;
    const int* rows = ei;
    const int* cols = ei + e;

    __half2* xwh; cudaGetSymbolAddress((void**)&xwh, g_xwh);
    float*   h;   cudaGetSymbolAddress((void**)&h,   g_h);
    float4*  wf1; cudaGetSymbolAddress((void**)&wf1, g_wf1);
    float4*  wf2; cudaGetSymbolAddress((void**)&wf2, g_wf2);

    // --- fused setup (deg zero + W fragments) ---
    k_setup<<<(n + 16384 + 255) / 256, 256>>>(W1, W2);
    k_count_deg<<<(e + 255) / 256, 256>>>(rows, e);
    k_scan_blocks<<<SCAN_NB, 256>>>();   // also computes dinv
    k_scan_write<<<SCAN_NB, 256>>>();    // fused tops + write, zeroes g_fill
    k_fill<<<(e + 255) / 256, 256>>>(rows, cols, e);

    const int gemm_blocks = (n + 63) / 64;   // 782
    const int agg_blocks  = (n + 15) / 16;   // 16 rows per 256-thread block

    // --- layer 1 ---
    k_gemm_tc<<<gemm_blocks, 256>>>(x, wf1, xwh);
    k_aggregate<<<agg_blocks, 256>>>((const uint4*)xwh, (const float4*)b1, (float4*)h, 1);

    // --- layer 2 ---
    k_gemm_tc<<<gemm_blocks, 256>>>(h, wf2, xwh);
    k_aggregate<<<agg_blocks, 256>>>((const uint4*)xwh, (const float4*)b2, (float4*)out, 0);
}